// round 11
// baseline (speedup 1.0000x reference)
#include <cuda_runtime.h>
#include <cuda_fp16.h>
#include <math.h>
#include <stdint.h>

// ---------------- problem constants ----------------
#define ZDIM   17728      // 3*56*56 + 64*128 + 128
#define ZPAD   17920      // 280*64 : padded K for GEMM1 (uniform split-K chunks)
#define HID    4096
#define NBATCH 128
#define N2PAD  17792      // 139*128, padded N for GEMM2 weights
#define NSTEPS 11
#define SPLITK1 8
#define NKB1   35         // 280/8 K-tiles per split group
#define NKB2   64         // 4096/64, GEMM2 full-K (no split)

// ---------------- device scratch (no allocs allowed) ----------------
__device__ __half g_W1h[(size_t)ZPAD * HID];       // W1 fp16 [k][n], k padded w/ zeros
__device__ __half g_W2h[(size_t)HID * N2PAD];      // W2 fp16 [k][n], n padded w/ zeros
__device__ __half g_zh [(size_t)NBATCH * ZPAD];    // fp16 z, k-padded w/ zeros
__device__ __half g_h  [(size_t)NBATCH * HID];     // fp16 hidden h
__device__ float  g_hpart[(size_t)SPLITK1 * NBATCH * HID];
__device__ float  g_emb[12 * NBATCH * 6];

// ---------------- time grid + embedding ----------------
__global__ void emb_kernel(const float* __restrict__ cur, const float* __restrict__ tar) {
    int b = threadIdx.x;
    if (b >= NBATCH) return;
    const float P[3] = {24.0f, 7.0f, 365.0f};
    float tc[3];
    for (int j = 0; j < 3; j++) tc[j] = cur[b * 3 + j];
    int r = 0;
    for (int j = 0; j < 3; j++) {
        float s = cur[b * 3 + j], e = tar[b * 3 + j];
        bool wrap = s > e;
        float ea = wrap ? e + P[j] : e;
        for (int k = 0; k < 4; k++) {
            float frac = (float)k / 3.0f;
            float inter = s + (ea - s) * frac;
            if (wrap) inter = fmodf(inter, P[j]);
            tc[j] = inter;
            for (int jj = 0; jj < 3; jj++) {
                float ph = 6.2831853071795864769f * tc[jj] / P[jj];
                g_emb[(r * NBATCH + b) * 6 + jj]     = sinf(ph);
                g_emb[(r * NBATCH + b) * 6 + 3 + jj] = cosf(ph);
            }
            r++;
        }
    }
}

// ---------------- z0 build (stride ZPAD for fp16 copy) ----------------
__global__ void z0_kernel(const float* __restrict__ freq, const int* __restrict__ seq,
                          const int* __restrict__ uid, const float* __restrict__ fuse,
                          const int* __restrict__ n_poi, float* __restrict__ zout) {
    int idx = blockIdx.x * blockDim.x + threadIdx.x;
    if (idx >= NBATCH * ZDIM) return;
    int b = idx / ZDIM;
    int c = idx - b * ZDIM;
    float v;
    if (c < 9408) {
        v = freq[b * 3136 + (c % 3136)];
    } else if (c < 17600) {
        int cc = c - 9408;
        int d = cc >> 6, l = cc & 63;
        v = fuse[(size_t)seq[b * 64 + l] * 128 + d];
    } else {
        int d = c - 17600;
        v = fuse[(size_t)(n_poi[0] + uid[b]) * 128 + d];
    }
    zout[idx] = v;
    g_zh[(size_t)b * ZPAD + c] = __float2half(v);
}

// zero the K-pad region of g_zh (cols [ZDIM, ZPAD)) — idempotent
__global__ void zpad_kernel() {
    int i = blockIdx.x * 256 + threadIdx.x;     // < 128 * 96  (half2 units)
    if (i >= NBATCH * (ZPAD - ZDIM) / 2) return;
    int b = i / ((ZPAD - ZDIM) / 2);
    int c = (i % ((ZPAD - ZDIM) / 2)) * 2;
    *(__half2*)(g_zh + (size_t)b * ZPAD + ZDIM + c) = __floats2half2_rn(0.f, 0.f);
}

// ---------------- fp32 -> fp16 weight conversion (8 floats/thread, 16B stores) ----------------
__global__ void convW1_kernel(const float* __restrict__ W1) {
    size_t i = (size_t)blockIdx.x * blockDim.x + threadIdx.x;   // oct over [ZPAD][HID]
    const size_t N = (size_t)ZPAD * HID / 8;
    if (i >= N) return;
    int k = (int)(i >> 9);                   // HID/8 = 512
    int n = (int)(i & 511) * 8;
    float4 v0, v1;
    if (k < ZDIM) {
        const float4* s = (const float4*)(W1 + (size_t)k * HID + n);
        v0 = s[0]; v1 = s[1];
    } else {
        v0 = v1 = make_float4(0.f, 0.f, 0.f, 0.f);
    }
    union { __half2 h[4]; uint4 u; } o;
    o.h[0] = __floats2half2_rn(v0.x, v0.y);
    o.h[1] = __floats2half2_rn(v0.z, v0.w);
    o.h[2] = __floats2half2_rn(v1.x, v1.y);
    o.h[3] = __floats2half2_rn(v1.z, v1.w);
    ((uint4*)g_W1h)[i] = o.u;
}

__global__ void convW2_kernel(const float* __restrict__ W2) {
    size_t i = (size_t)blockIdx.x * blockDim.x + threadIdx.x;   // oct over [HID][N2PAD]
    const size_t N = (size_t)HID * N2PAD / 8;
    if (i >= N) return;
    int k = (int)(i / (N2PAD / 8));
    int n = (int)(i % (N2PAD / 8)) * 8;
    float4 v0, v1;
    if (n < ZDIM) {                          // ZDIM%8==0 -> full oct in range
        const float4* s = (const float4*)(W2 + (size_t)k * ZDIM + n);
        v0 = s[0]; v1 = s[1];
    } else {
        v0 = v1 = make_float4(0.f, 0.f, 0.f, 0.f);
    }
    union { __half2 h[4]; uint4 u; } o;
    o.h[0] = __floats2half2_rn(v0.x, v0.y);
    o.h[1] = __floats2half2_rn(v0.z, v0.w);
    o.h[2] = __floats2half2_rn(v1.x, v1.y);
    o.h[3] = __floats2half2_rn(v1.z, v1.w);
    ((uint4*)g_W2h)[i] = o.u;
}

// ---------------- GEMM: 128x128 CTA tile, 4 warps (64x64 each), BK=64, cp.async pipeline ----------------
// smem stage: A tile at +0 (16KB, 128B rows), B tile at +16384 (16KB, 256B rows)
#define STAGEB 32768
#define SMEM0 (3 * STAGEB)    // 98304  : MODE 0, 2 CTAs/SM
#define SMEM1 (5 * STAGEB)    // 163840 : MODE 1, 1 CTA/SM, deep pipeline

__device__ __forceinline__ uint32_t s2u(const void* p) {
    return (uint32_t)__cvta_generic_to_shared(p);
}
__device__ __forceinline__ void cp16(uint32_t dst, const void* src) {
    asm volatile("cp.async.cg.shared.global [%0],[%1],16;\n" :: "r"(dst), "l"(src));
}

// MODE 0: g_hpart[split] = zh @ W1h          (split-K 8, NKB=35, 3 stages)
// MODE 1: z += h @ W2h + b2, refresh g_zh    (no split,   NKB=64, 5 stages, fused epilogue)
template <int MODE>
__global__ __launch_bounds__(128, (MODE == 0) ? 2 : 1)
void gemm_kernel(const float* __restrict__ bias, float* __restrict__ zio) {
    constexpr int LDA  = (MODE == 0) ? ZPAD : HID;
    constexpr int LDB  = (MODE == 0) ? HID  : N2PAD;
    constexpr int NKB  = (MODE == 0) ? NKB1 : NKB2;
    constexpr int NSTG = (MODE == 0) ? 3    : 5;

    extern __shared__ char sm[];
    const uint32_t smb = s2u(sm);
    const int tid = threadIdx.x, lane = tid & 31, warp = tid >> 5;
    const int wm = warp >> 1, wn = warp & 1;      // 2x2 warp grid, 64x64 tiles
    const int n0 = blockIdx.x * 128;
    const int kb0 = (MODE == 0) ? blockIdx.y * NKB : 0;

    const __half* A = (MODE == 0) ? g_zh : g_h;
    const __half* B = (MODE == 0) ? g_W1h : g_W2h;

    // ---- hoisted load setup ----
    const int am = tid >> 3, ac = tid & 7;
    const int bk = tid >> 4, bc = tid & 15;
    const __half* aptr = A + (size_t)am * LDA + kb0 * 64 + ac * 8;
    const __half* bptr = B + (size_t)(kb0 * 64 + bk) * LDB + n0 + bc * 8;
    const uint32_t aoff = (uint32_t)(am * 128 + ((ac ^ (am & 7)) << 4));
    const uint32_t boff = 16384u + (uint32_t)(bk * 256 + ((bc ^ (bk & 7)) << 4));

    // ---- hoisted ldmatrix addressing ----
    const int hi = lane >> 4, lo7 = lane & 7, lo15 = lane & 15;
    uint32_t baseA[4], swA[4], preB[4];
#pragma unroll
    for (int f = 0; f < 4; f++) baseA[f] = (uint32_t)((wm * 64 + f * 16 + lo15) * 128);
#pragma unroll
    for (int ks = 0; ks < 4; ks++) swA[ks] = (uint32_t)(((ks * 2 + hi) ^ lo7) << 4);
#pragma unroll
    for (int h = 0; h < 4; h++)
        preB[h] = 16384u + (uint32_t)((((wn * 8 + h * 2 + hi) ^ lo7) << 4) + lo15 * 256);

    float acc[4][8][4];
#pragma unroll
    for (int f = 0; f < 4; f++)
#pragma unroll
        for (int t = 0; t < 8; t++)
#pragma unroll
            for (int i = 0; i < 4; i++) acc[f][t][i] = 0.0f;

    auto load_stage = [&](uint32_t stage) {
#pragma unroll
        for (int i = 0; i < 8; i++) {
            cp16(stage + aoff + i * 2048, aptr + (size_t)i * 16 * LDA);
            cp16(stage + boff + i * 2048, bptr + (size_t)i * 8 * LDB);
        }
        aptr += 64;
        bptr += (size_t)64 * LDB;
    };

    uint32_t st[NSTG];
#pragma unroll
    for (int s = 0; s < NSTG; s++) st[s] = smb + s * STAGEB;

    // prologue: tiles 0..NSTG-2
#pragma unroll
    for (int s = 0; s < NSTG - 1; s++) {
        load_stage(st[s]);
        asm volatile("cp.async.commit_group;\n");
    }

#pragma unroll 1
    for (int kb = 0; kb < NKB; kb++) {
        asm volatile("cp.async.wait_group %0;\n" :: "n"(NSTG - 2));
        __syncthreads();
        if (kb + NSTG - 1 < NKB) load_stage(st[NSTG - 1]);
        asm volatile("cp.async.commit_group;\n");

        const uint32_t s0 = st[0];
#pragma unroll
        for (int ks = 0; ks < 4; ks++) {
            uint32_t a[4][4], bf[8][2];
#pragma unroll
            for (int f = 0; f < 4; f++) {
                asm volatile("ldmatrix.sync.aligned.m8n8.x4.shared.b16 {%0,%1,%2,%3},[%4];\n"
                             : "=r"(a[f][0]), "=r"(a[f][1]), "=r"(a[f][2]), "=r"(a[f][3])
                             : "r"(s0 + baseA[f] + swA[ks]));
            }
#pragma unroll
            for (int h = 0; h < 4; h++) {
                uint32_t r0, r1, r2, r3;
                asm volatile("ldmatrix.sync.aligned.m8n8.x4.trans.shared.b16 {%0,%1,%2,%3},[%4];\n"
                             : "=r"(r0), "=r"(r1), "=r"(r2), "=r"(r3)
                             : "r"(s0 + preB[h] + ks * 4096));
                bf[h * 2][0] = r0; bf[h * 2][1] = r1;
                bf[h * 2 + 1][0] = r2; bf[h * 2 + 1][1] = r3;
            }
#pragma unroll
            for (int f = 0; f < 4; f++)
#pragma unroll
                for (int t = 0; t < 8; t++) {
                    asm volatile(
                        "mma.sync.aligned.m16n8k16.row.col.f32.f16.f16.f32 "
                        "{%0,%1,%2,%3},{%4,%5,%6,%7},{%8,%9},{%0,%1,%2,%3};\n"
                        : "+f"(acc[f][t][0]), "+f"(acc[f][t][1]),
                          "+f"(acc[f][t][2]), "+f"(acc[f][t][3])
                        : "r"(a[f][0]), "r"(a[f][1]), "r"(a[f][2]), "r"(a[f][3]),
                          "r"(bf[t][0]), "r"(bf[t][1]));
                }
        }
        // rotate stages left
        uint32_t tmp = st[0];
#pragma unroll
        for (int s = 0; s < NSTG - 1; s++) st[s] = st[s + 1];
        st[NSTG - 1] = tmp;
    }

    if (MODE == 0) {
        // epilogue: fp32 partials
        float* part = g_hpart + (size_t)blockIdx.y * NBATCH * HID;
#pragma unroll
        for (int f = 0; f < 4; f++) {
            int row = wm * 64 + f * 16 + (lane >> 2);
#pragma unroll
            for (int t = 0; t < 8; t++) {
                int col = n0 + wn * 64 + t * 8 + ((lane & 3) << 1);
                *(float2*)(part + (size_t)row * HID + col)       = make_float2(acc[f][t][0], acc[f][t][1]);
                *(float2*)(part + (size_t)(row + 8) * HID + col) = make_float2(acc[f][t][2], acc[f][t][3]);
            }
        }
    } else {
        // fused epilogue: z += acc + b2; refresh fp16 z
#pragma unroll
        for (int f = 0; f < 4; f++) {
            int row = wm * 64 + f * 16 + (lane >> 2);
#pragma unroll
            for (int t = 0; t < 8; t++) {
                int col = n0 + wn * 64 + t * 8 + ((lane & 3) << 1);
                if (col < ZDIM) {
                    float2 bv = *(const float2*)(bias + col);
                    size_t o0 = (size_t)row * ZDIM + col;
                    float2 z0 = *(float2*)(zio + o0);
                    float v0 = z0.x + bv.x + acc[f][t][0];
                    float v1 = z0.y + bv.y + acc[f][t][1];
                    *(float2*)(zio + o0) = make_float2(v0, v1);
                    *(__half2*)(g_zh + (size_t)row * ZPAD + col) = __floats2half2_rn(v0, v1);
                    size_t o1 = (size_t)(row + 8) * ZDIM + col;
                    float2 z1 = *(float2*)(zio + o1);
                    float v2 = z1.x + bv.x + acc[f][t][2];
                    float v3 = z1.y + bv.y + acc[f][t][3];
                    *(float2*)(zio + o1) = make_float2(v2, v3);
                    *(__half2*)(g_zh + (size_t)(row + 8) * ZPAD + col) = __floats2half2_rn(v2, v3);
                }
            }
        }
    }
}

// ---------------- GEMM1 reduce + bias + time-embedding tail + tanh ----------------
__global__ void reduce_tanh_kernel(const float* __restrict__ W1, const float* __restrict__ b1, int t) {
    int idx = blockIdx.x * 256 + threadIdx.x;      // < 128*4096
    int b = idx >> 12, n = idx & 4095;
    float s = b1[n];
#pragma unroll
    for (int p = 0; p < SPLITK1; p++)
        s += g_hpart[(size_t)p * NBATCH * HID + idx];
    const float* e0 = g_emb + (t * NBATCH + b) * 6;
    const float* e1 = e0 + NBATCH * 6;
#pragma unroll
    for (int j = 0; j < 6; j++) s += e0[j] * W1[(size_t)(ZDIM + j) * HID + n];
#pragma unroll
    for (int j = 0; j < 6; j++) s += e1[j] * W1[(size_t)(ZDIM + 6 + j) * HID + n];
    g_h[idx] = __float2half(tanhf(s));
}

// ---------------- launcher ----------------
extern "C" void kernel_launch(void* const* d_in, const int* in_sizes, int n_in,
                              void* d_out, int out_size) {
    const float* input_freq = (const float*)d_in[0];
    const int*   input_seq  = (const int*)  d_in[1];
    const int*   uid        = (const int*)  d_in[2];
    const float* cur_time   = (const float*)d_in[3];
    const float* tar_time   = (const float*)d_in[4];
    const float* fuse       = (const float*)d_in[5];
    const float* W1         = (const float*)d_in[6];
    const float* b1         = (const float*)d_in[7];
    const float* W2         = (const float*)d_in[8];
    const float* b2         = (const float*)d_in[9];
    const int*   n_poi      = (const int*)  d_in[10];
    float* z = (float*)d_out;

    cudaFuncSetAttribute(gemm_kernel<0>, cudaFuncAttributeMaxDynamicSharedMemorySize, SMEM0);
    cudaFuncSetAttribute(gemm_kernel<1>, cudaFuncAttributeMaxDynamicSharedMemorySize, SMEM1);

    emb_kernel<<<1, 128>>>(cur_time, tar_time);
    z0_kernel<<<(NBATCH * ZDIM + 511) / 512, 512>>>(input_freq, input_seq, uid, fuse, n_poi, z);
    zpad_kernel<<<(NBATCH * (ZPAD - ZDIM) / 2 + 255) / 256, 256>>>();

    {   // weight conversion, once per launch (16B loads+stores)
        size_t n1 = (size_t)ZPAD * HID / 8;
        size_t n2 = (size_t)HID * N2PAD / 8;
        convW1_kernel<<<(unsigned)((n1 + 255) / 256), 256>>>(W1);
        convW2_kernel<<<(unsigned)((n2 + 255) / 256), 256>>>(W2);
    }

    for (int t = 0; t < NSTEPS; t++) {
        gemm_kernel<0><<<dim3(HID / 128, SPLITK1), 128, SMEM0>>>(nullptr, nullptr);
        reduce_tanh_kernel<<<NBATCH * HID / 256, 256>>>(W1, b1, t);
        gemm_kernel<1><<<dim3(N2PAD / 128, 1), 128, SMEM1>>>(b2, z);
    }
}

// round 12
// speedup vs baseline: 1.1968x; 1.1968x over previous
#include <cuda_runtime.h>
#include <cuda_fp16.h>
#include <math.h>
#include <stdint.h>

// ---------------- problem constants ----------------
#define ZDIM   17728      // 3*56*56 + 64*128 + 128
#define ZPAD   18432      // 288*64 : padded K for GEMM1 (9 uniform split-K chunks)
#define HID    4096
#define NBATCH 128
#define N2PAD  17792      // 139*128, padded N for GEMM2
#define NSTEPS 11
#define SPLITK1 9
#define NKB1   32         // 288/9 K-tiles per split group (compile-time)
#define SPLITK2 2
#define NKB2   32         // 64/2

// ---------------- device scratch (no allocs allowed) ----------------
__device__ __half g_W1h[(size_t)ZPAD * HID];       // W1 fp16 [k][n], k padded w/ zeros
__device__ __half g_W2h[(size_t)HID * N2PAD];      // W2 fp16 [k][n], n padded w/ zeros
__device__ __half g_zh [(size_t)NBATCH * ZPAD];    // fp16 z, k-padded w/ zeros
__device__ __half g_h  [(size_t)NBATCH * HID];     // fp16 hidden h
__device__ float  g_hpart [(size_t)SPLITK1 * NBATCH * HID];
__device__ float  g_h2part[(size_t)SPLITK2 * NBATCH * N2PAD];
__device__ float  g_emb[12 * NBATCH * 6];

// ---------------- time grid + embedding ----------------
__global__ void emb_kernel(const float* __restrict__ cur, const float* __restrict__ tar) {
    int b = threadIdx.x;
    if (b >= NBATCH) return;
    const float P[3] = {24.0f, 7.0f, 365.0f};
    float tc[3];
    for (int j = 0; j < 3; j++) tc[j] = cur[b * 3 + j];
    int r = 0;
    for (int j = 0; j < 3; j++) {
        float s = cur[b * 3 + j], e = tar[b * 3 + j];
        bool wrap = s > e;
        float ea = wrap ? e + P[j] : e;
        for (int k = 0; k < 4; k++) {
            float frac = (float)k / 3.0f;
            float inter = s + (ea - s) * frac;
            if (wrap) inter = fmodf(inter, P[j]);
            tc[j] = inter;
            for (int jj = 0; jj < 3; jj++) {
                float ph = 6.2831853071795864769f * tc[jj] / P[jj];
                g_emb[(r * NBATCH + b) * 6 + jj]     = sinf(ph);
                g_emb[(r * NBATCH + b) * 6 + 3 + jj] = cosf(ph);
            }
            r++;
        }
    }
}

// ---------------- z0 build (stride ZPAD for fp16 copy) ----------------
__global__ void z0_kernel(const float* __restrict__ freq, const int* __restrict__ seq,
                          const int* __restrict__ uid, const float* __restrict__ fuse,
                          const int* __restrict__ n_poi, float* __restrict__ zout) {
    int idx = blockIdx.x * blockDim.x + threadIdx.x;
    if (idx >= NBATCH * ZDIM) return;
    int b = idx / ZDIM;
    int c = idx - b * ZDIM;
    float v;
    if (c < 9408) {
        v = freq[b * 3136 + (c % 3136)];
    } else if (c < 17600) {
        int cc = c - 9408;
        int d = cc >> 6, l = cc & 63;
        v = fuse[(size_t)seq[b * 64 + l] * 128 + d];
    } else {
        int d = c - 17600;
        v = fuse[(size_t)(n_poi[0] + uid[b]) * 128 + d];
    }
    zout[idx] = v;
    g_zh[(size_t)b * ZPAD + c] = __float2half(v);
}

// zero the K-pad region of g_zh (cols [ZDIM, ZPAD)) — idempotent
__global__ void zpad_kernel() {
    int i = blockIdx.x * 256 + threadIdx.x;     // half2 units
    if (i >= NBATCH * (ZPAD - ZDIM) / 2) return;
    int b = i / ((ZPAD - ZDIM) / 2);
    int c = (i % ((ZPAD - ZDIM) / 2)) * 2;
    *(__half2*)(g_zh + (size_t)b * ZPAD + ZDIM + c) = __floats2half2_rn(0.f, 0.f);
}

// ---------------- fp32 -> fp16 weight conversion (8 floats/thread, 16B stores) ----------------
__global__ void convW1_kernel(const float* __restrict__ W1) {
    size_t i = (size_t)blockIdx.x * blockDim.x + threadIdx.x;   // oct over [ZPAD][HID]
    const size_t N = (size_t)ZPAD * HID / 8;
    if (i >= N) return;
    int k = (int)(i >> 9);                   // HID/8 = 512
    int n = (int)(i & 511) * 8;
    float4 v0, v1;
    if (k < ZDIM) {
        const float4* s = (const float4*)(W1 + (size_t)k * HID + n);
        v0 = s[0]; v1 = s[1];
    } else {
        v0 = v1 = make_float4(0.f, 0.f, 0.f, 0.f);
    }
    union { __half2 h[4]; uint4 u; } o;
    o.h[0] = __floats2half2_rn(v0.x, v0.y);
    o.h[1] = __floats2half2_rn(v0.z, v0.w);
    o.h[2] = __floats2half2_rn(v1.x, v1.y);
    o.h[3] = __floats2half2_rn(v1.z, v1.w);
    ((uint4*)g_W1h)[i] = o.u;
}

__global__ void convW2_kernel(const float* __restrict__ W2) {
    size_t i = (size_t)blockIdx.x * blockDim.x + threadIdx.x;   // oct over [HID][N2PAD]
    const size_t N = (size_t)HID * N2PAD / 8;
    if (i >= N) return;
    int k = (int)(i / (N2PAD / 8));
    int n = (int)(i % (N2PAD / 8)) * 8;
    float4 v0, v1;
    if (n < ZDIM) {                          // ZDIM%8==0 -> full oct in range
        const float4* s = (const float4*)(W2 + (size_t)k * ZDIM + n);
        v0 = s[0]; v1 = s[1];
    } else {
        v0 = v1 = make_float4(0.f, 0.f, 0.f, 0.f);
    }
    union { __half2 h[4]; uint4 u; } o;
    o.h[0] = __floats2half2_rn(v0.x, v0.y);
    o.h[1] = __floats2half2_rn(v0.z, v0.w);
    o.h[2] = __floats2half2_rn(v1.x, v1.y);
    o.h[3] = __floats2half2_rn(v1.z, v1.w);
    ((uint4*)g_W2h)[i] = o.u;
}

// ---------------- GEMM: 128x128 CTA tile, 4 warps (64x64 each), BK=64, 3-stage cp.async ----------------
// smem stage: A tile at +0 (16KB, 128B rows), B tile at +16384 (16KB, 256B rows), SW swizzle
#define STAGEB 32768
#define SMEM_BYTES (3 * STAGEB)    // 98304 -> 2 CTAs/SM

__device__ __forceinline__ uint32_t s2u(const void* p) {
    return (uint32_t)__cvta_generic_to_shared(p);
}
__device__ __forceinline__ void cp16(uint32_t dst, const void* src) {
    asm volatile("cp.async.cg.shared.global [%0],[%1],16;\n" :: "r"(dst), "l"(src));
}

// MODE 0: g_hpart [split] = zh @ W1h   (split-K 9, NKB=32)
// MODE 1: g_h2part[split] = h  @ W2h   (split-K 2, NKB=32)
template <int MODE>
__global__ __launch_bounds__(128, 2) void gemm_kernel() {
    constexpr int LDA = (MODE == 0) ? ZPAD : HID;
    constexpr int LDB = (MODE == 0) ? HID  : N2PAD;
    constexpr int LDO = (MODE == 0) ? HID  : N2PAD;
    constexpr int NKB = (MODE == 0) ? NKB1 : NKB2;

    extern __shared__ char sm[];
    const uint32_t smb = s2u(sm);
    const int tid = threadIdx.x, lane = tid & 31, warp = tid >> 5;
    const int wm = warp >> 1, wn = warp & 1;      // 2x2 warp grid, 64x64 tiles
    const int n0 = blockIdx.x * 128;
    const int kb0 = blockIdx.y * NKB;

    const __half* A = (MODE == 0) ? g_zh : g_h;
    const __half* B = (MODE == 0) ? g_W1h : g_W2h;
    float* part = ((MODE == 0) ? g_hpart : g_h2part)
                + (size_t)blockIdx.y * NBATCH * LDO;

    // ---- hoisted load setup (128 threads: 8 A-chunks + 8 B-chunks each) ----
    const int am = tid >> 3, ac = tid & 7;      // A: rows am + i*16, chunk ac
    const int bk = tid >> 4, bc = tid & 15;     // B: rows bk + i*8,  chunk bc
    const __half* aptr = A + (size_t)am * LDA + kb0 * 64 + ac * 8;
    const __half* bptr = B + (size_t)(kb0 * 64 + bk) * LDB + n0 + bc * 8;
    const uint32_t aoff = (uint32_t)(am * 128 + ((ac ^ (am & 7)) << 4));          // bytes
    const uint32_t boff = 16384u + (uint32_t)(bk * 256 + ((bc ^ (bk & 7)) << 4)); // bytes

    // ---- hoisted ldmatrix addressing ----
    const int hi = lane >> 4, lo7 = lane & 7, lo15 = lane & 15;
    uint32_t baseA[4], swA[4], preB[4];
#pragma unroll
    for (int f = 0; f < 4; f++) baseA[f] = (uint32_t)((wm * 64 + f * 16 + lo15) * 128);
#pragma unroll
    for (int ks = 0; ks < 4; ks++) swA[ks] = (uint32_t)(((ks * 2 + hi) ^ lo7) << 4);
#pragma unroll
    for (int h = 0; h < 4; h++)
        preB[h] = 16384u + (uint32_t)((((wn * 8 + h * 2 + hi) ^ lo7) << 4) + lo15 * 256);

    float acc[4][8][4];
#pragma unroll
    for (int f = 0; f < 4; f++)
#pragma unroll
        for (int t = 0; t < 8; t++)
#pragma unroll
            for (int i = 0; i < 4; i++) acc[f][t][i] = 0.0f;

    auto load_stage = [&](uint32_t stage) {
#pragma unroll
        for (int i = 0; i < 8; i++) {
            cp16(stage + aoff + i * 2048, aptr + (size_t)i * 16 * LDA);
            cp16(stage + boff + i * 2048, bptr + (size_t)i * 8 * LDB);
        }
        aptr += 64;
        bptr += (size_t)64 * LDB;
    };

    uint32_t s0 = smb, s1 = smb + STAGEB, s2 = smb + 2 * STAGEB;

    // prologue: tiles 0,1 into stages 0,1
    load_stage(s0);
    asm volatile("cp.async.commit_group;\n");
    load_stage(s1);
    asm volatile("cp.async.commit_group;\n");

#pragma unroll 1
    for (int kb = 0; kb < NKB; kb++) {
        asm volatile("cp.async.wait_group %0;\n" :: "n"(1));
        __syncthreads();
        if (kb + 2 < NKB) load_stage(s2);
        asm volatile("cp.async.commit_group;\n");

#pragma unroll
        for (int ks = 0; ks < 4; ks++) {
            uint32_t a[4][4], bf[8][2];
#pragma unroll
            for (int f = 0; f < 4; f++) {
                asm volatile("ldmatrix.sync.aligned.m8n8.x4.shared.b16 {%0,%1,%2,%3},[%4];\n"
                             : "=r"(a[f][0]), "=r"(a[f][1]), "=r"(a[f][2]), "=r"(a[f][3])
                             : "r"(s0 + baseA[f] + swA[ks]));
            }
#pragma unroll
            for (int h = 0; h < 4; h++) {
                uint32_t r0, r1, r2, r3;
                asm volatile("ldmatrix.sync.aligned.m8n8.x4.trans.shared.b16 {%0,%1,%2,%3},[%4];\n"
                             : "=r"(r0), "=r"(r1), "=r"(r2), "=r"(r3)
                             : "r"(s0 + preB[h] + ks * 4096));
                bf[h * 2][0] = r0; bf[h * 2][1] = r1;
                bf[h * 2 + 1][0] = r2; bf[h * 2 + 1][1] = r3;
            }
#pragma unroll
            for (int f = 0; f < 4; f++)
#pragma unroll
                for (int t = 0; t < 8; t++) {
                    asm volatile(
                        "mma.sync.aligned.m16n8k16.row.col.f32.f16.f16.f32 "
                        "{%0,%1,%2,%3},{%4,%5,%6,%7},{%8,%9},{%0,%1,%2,%3};\n"
                        : "+f"(acc[f][t][0]), "+f"(acc[f][t][1]),
                          "+f"(acc[f][t][2]), "+f"(acc[f][t][3])
                        : "r"(a[f][0]), "r"(a[f][1]), "r"(a[f][2]), "r"(a[f][3]),
                          "r"(bf[t][0]), "r"(bf[t][1]));
                }
        }
        // rotate stages
        uint32_t tmp = s0; s0 = s1; s1 = s2; s2 = tmp;
    }

    // epilogue: fp32 partials
#pragma unroll
    for (int f = 0; f < 4; f++) {
        int row = wm * 64 + f * 16 + (lane >> 2);
#pragma unroll
        for (int t = 0; t < 8; t++) {
            int col = n0 + wn * 64 + t * 8 + ((lane & 3) << 1);
            *(float2*)(part + (size_t)row * LDO + col)       = make_float2(acc[f][t][0], acc[f][t][1]);
            *(float2*)(part + (size_t)(row + 8) * LDO + col) = make_float2(acc[f][t][2], acc[f][t][3]);
        }
    }
}

// ---------------- GEMM1 reduce + bias + time-embedding tail + tanh ----------------
__global__ void reduce_tanh_kernel(const float* __restrict__ W1, const float* __restrict__ b1, int t) {
    int idx = blockIdx.x * 256 + threadIdx.x;      // < 128*4096
    int b = idx >> 12, n = idx & 4095;
    float s = b1[n];
#pragma unroll
    for (int p = 0; p < SPLITK1; p++)
        s += g_hpart[(size_t)p * NBATCH * HID + idx];
    const float* e0 = g_emb + (t * NBATCH + b) * 6;
    const float* e1 = e0 + NBATCH * 6;
#pragma unroll
    for (int j = 0; j < 6; j++) s += e0[j] * W1[(size_t)(ZDIM + j) * HID + n];
#pragma unroll
    for (int j = 0; j < 6; j++) s += e1[j] * W1[(size_t)(ZDIM + 6 + j) * HID + n];
    g_h[idx] = __float2half(tanhf(s));
}

// ---------------- GEMM2 reduce: z += p0 + p1 + b2, refresh fp16 z ----------------
__global__ void zupdate_kernel(const float* __restrict__ b2, float* __restrict__ z) {
    int idx = blockIdx.x * 256 + threadIdx.x;
    if (idx >= NBATCH * ZDIM) return;
    int row = idx / ZDIM;
    int col = idx - row * ZDIM;
    size_t po = (size_t)row * N2PAD + col;
    float v = z[idx] + b2[col]
            + g_h2part[po]
            + g_h2part[(size_t)NBATCH * N2PAD + po];
    z[idx] = v;
    g_zh[(size_t)row * ZPAD + col] = __float2half(v);
}

// ---------------- launcher ----------------
extern "C" void kernel_launch(void* const* d_in, const int* in_sizes, int n_in,
                              void* d_out, int out_size) {
    const float* input_freq = (const float*)d_in[0];
    const int*   input_seq  = (const int*)  d_in[1];
    const int*   uid        = (const int*)  d_in[2];
    const float* cur_time   = (const float*)d_in[3];
    const float* tar_time   = (const float*)d_in[4];
    const float* fuse       = (const float*)d_in[5];
    const float* W1         = (const float*)d_in[6];
    const float* b1         = (const float*)d_in[7];
    const float* W2         = (const float*)d_in[8];
    const float* b2         = (const float*)d_in[9];
    const int*   n_poi      = (const int*)  d_in[10];
    float* z = (float*)d_out;

    cudaFuncSetAttribute(gemm_kernel<0>, cudaFuncAttributeMaxDynamicSharedMemorySize, SMEM_BYTES);
    cudaFuncSetAttribute(gemm_kernel<1>, cudaFuncAttributeMaxDynamicSharedMemorySize, SMEM_BYTES);

    emb_kernel<<<1, 128>>>(cur_time, tar_time);
    z0_kernel<<<(NBATCH * ZDIM + 511) / 512, 512>>>(input_freq, input_seq, uid, fuse, n_poi, z);
    zpad_kernel<<<(NBATCH * (ZPAD - ZDIM) / 2 + 255) / 256, 256>>>();

    {   // weight conversion, once per launch (16B loads+stores)
        size_t n1 = (size_t)ZPAD * HID / 8;
        size_t n2 = (size_t)HID * N2PAD / 8;
        convW1_kernel<<<(unsigned)((n1 + 255) / 256), 256>>>(W1);
        convW2_kernel<<<(unsigned)((n2 + 255) / 256), 256>>>(W2);
    }

    for (int t = 0; t < NSTEPS; t++) {
        gemm_kernel<0><<<dim3(HID / 128, SPLITK1), 128, SMEM_BYTES>>>();
        reduce_tanh_kernel<<<NBATCH * HID / 256, 256>>>(W1, b1, t);
        gemm_kernel<1><<<dim3(N2PAD / 128, SPLITK2), 128, SMEM_BYTES>>>();
        zupdate_kernel<<<(NBATCH * ZDIM + 255) / 256, 256>>>(b2, z);
    }
}

// round 13
// speedup vs baseline: 1.2171x; 1.0170x over previous
#include <cuda_runtime.h>
#include <cuda_fp16.h>
#include <math.h>
#include <stdint.h>

// ---------------- problem constants ----------------
#define ZDIM   17728      // 3*56*56 + 64*128 + 128
#define ZPAD   18432      // 288*64 : padded K for GEMM1 (9 uniform split-K chunks)
#define HID    4096
#define NBATCH 128
#define N2PAD  17792      // 139*128, padded N for GEMM2
#define NSTEPS 11
#define SPLITK1 9
#define NKB1   32         // 288/9 K-tiles per split group (compile-time)
#define SPLITK2 2
#define NKB2   32         // 64/2

// ---------------- device scratch (no allocs allowed) ----------------
__device__ __half g_W1h[(size_t)ZPAD * HID];       // W1 fp16 [k][n], k padded w/ zeros
__device__ __half g_W2h[(size_t)HID * N2PAD];      // W2 fp16 [k][n], n padded w/ zeros
__device__ __half g_zh [(size_t)NBATCH * ZPAD];    // fp16 z, k-padded w/ zeros
__device__ __half g_h  [(size_t)NBATCH * HID];     // fp16 hidden h
__device__ float  g_hpart [(size_t)SPLITK1 * NBATCH * HID];
__device__ float  g_h2part[(size_t)SPLITK2 * NBATCH * N2PAD];
__device__ float  g_emb[12 * NBATCH * 6];

// ---------------- time grid + embedding ----------------
__global__ void emb_kernel(const float* __restrict__ cur, const float* __restrict__ tar) {
    int b = threadIdx.x;
    if (b >= NBATCH) return;
    const float P[3] = {24.0f, 7.0f, 365.0f};
    float tc[3];
    for (int j = 0; j < 3; j++) tc[j] = cur[b * 3 + j];
    int r = 0;
    for (int j = 0; j < 3; j++) {
        float s = cur[b * 3 + j], e = tar[b * 3 + j];
        bool wrap = s > e;
        float ea = wrap ? e + P[j] : e;
        for (int k = 0; k < 4; k++) {
            float frac = (float)k / 3.0f;
            float inter = s + (ea - s) * frac;
            if (wrap) inter = fmodf(inter, P[j]);
            tc[j] = inter;
            for (int jj = 0; jj < 3; jj++) {
                float ph = 6.2831853071795864769f * tc[jj] / P[jj];
                g_emb[(r * NBATCH + b) * 6 + jj]     = sinf(ph);
                g_emb[(r * NBATCH + b) * 6 + 3 + jj] = cosf(ph);
            }
            r++;
        }
    }
}

// ---------------- z0 build (stride ZPAD for fp16 copy) ----------------
__global__ void z0_kernel(const float* __restrict__ freq, const int* __restrict__ seq,
                          const int* __restrict__ uid, const float* __restrict__ fuse,
                          const int* __restrict__ n_poi, float* __restrict__ zout) {
    int idx = blockIdx.x * blockDim.x + threadIdx.x;
    if (idx >= NBATCH * ZDIM) return;
    int b = idx / ZDIM;
    int c = idx - b * ZDIM;
    float v;
    if (c < 9408) {
        v = freq[b * 3136 + (c % 3136)];
    } else if (c < 17600) {
        int cc = c - 9408;
        int d = cc >> 6, l = cc & 63;
        v = fuse[(size_t)seq[b * 64 + l] * 128 + d];
    } else {
        int d = c - 17600;
        v = fuse[(size_t)(n_poi[0] + uid[b]) * 128 + d];
    }
    zout[idx] = v;
    g_zh[(size_t)b * ZPAD + c] = __float2half(v);
}

// zero the K-pad region of g_zh (cols [ZDIM, ZPAD)) — idempotent
__global__ void zpad_kernel() {
    int i = blockIdx.x * 256 + threadIdx.x;     // half2 units
    if (i >= NBATCH * (ZPAD - ZDIM) / 2) return;
    int b = i / ((ZPAD - ZDIM) / 2);
    int c = (i % ((ZPAD - ZDIM) / 2)) * 2;
    *(__half2*)(g_zh + (size_t)b * ZPAD + ZDIM + c) = __floats2half2_rn(0.f, 0.f);
}

// ---------------- fp32 -> fp16 weight conversion (8 floats/thread, 16B stores) ----------------
__global__ void convW1_kernel(const float* __restrict__ W1) {
    size_t i = (size_t)blockIdx.x * blockDim.x + threadIdx.x;   // oct over [ZPAD][HID]
    const size_t N = (size_t)ZPAD * HID / 8;
    if (i >= N) return;
    int k = (int)(i >> 9);                   // HID/8 = 512
    int n = (int)(i & 511) * 8;
    float4 v0, v1;
    if (k < ZDIM) {
        const float4* s = (const float4*)(W1 + (size_t)k * HID + n);
        v0 = s[0]; v1 = s[1];
    } else {
        v0 = v1 = make_float4(0.f, 0.f, 0.f, 0.f);
    }
    union { __half2 h[4]; uint4 u; } o;
    o.h[0] = __floats2half2_rn(v0.x, v0.y);
    o.h[1] = __floats2half2_rn(v0.z, v0.w);
    o.h[2] = __floats2half2_rn(v1.x, v1.y);
    o.h[3] = __floats2half2_rn(v1.z, v1.w);
    ((uint4*)g_W1h)[i] = o.u;
}

__global__ void convW2_kernel(const float* __restrict__ W2) {
    size_t i = (size_t)blockIdx.x * blockDim.x + threadIdx.x;   // oct over [HID][N2PAD]
    const size_t N = (size_t)HID * N2PAD / 8;
    if (i >= N) return;
    int k = (int)(i / (N2PAD / 8));
    int n = (int)(i % (N2PAD / 8)) * 8;
    float4 v0, v1;
    if (n < ZDIM) {                          // ZDIM%8==0 -> full oct in range
        const float4* s = (const float4*)(W2 + (size_t)k * ZDIM + n);
        v0 = s[0]; v1 = s[1];
    } else {
        v0 = v1 = make_float4(0.f, 0.f, 0.f, 0.f);
    }
    union { __half2 h[4]; uint4 u; } o;
    o.h[0] = __floats2half2_rn(v0.x, v0.y);
    o.h[1] = __floats2half2_rn(v0.z, v0.w);
    o.h[2] = __floats2half2_rn(v1.x, v1.y);
    o.h[3] = __floats2half2_rn(v1.z, v1.w);
    ((uint4*)g_W2h)[i] = o.u;
}

// ---------------- GEMM: 128x128 CTA tile, 4 warps (64x64 each), BK=64, 3-stage cp.async ----------------
#define STAGEB 32768
#define SMEM_BYTES (3 * STAGEB)    // 98304 -> 2 CTAs/SM

__device__ __forceinline__ uint32_t s2u(const void* p) {
    return (uint32_t)__cvta_generic_to_shared(p);
}
__device__ __forceinline__ void cp16(uint32_t dst, const void* src) {
    asm volatile("cp.async.cg.shared.global [%0],[%1],16;\n" :: "r"(dst), "l"(src));
}

// MODE 0: g_hpart [split] = zh @ W1h   (split-K 9, NKB=32)
// MODE 1: g_h2part[split] = h  @ W2h   (split-K 2, NKB=32)
template <int MODE>
__global__ __launch_bounds__(128, 2) void gemm_kernel() {
    constexpr int LDA = (MODE == 0) ? ZPAD : HID;
    constexpr int LDB = (MODE == 0) ? HID  : N2PAD;
    constexpr int LDO = (MODE == 0) ? HID  : N2PAD;
    constexpr int NKB = (MODE == 0) ? NKB1 : NKB2;

    extern __shared__ char sm[];
    const uint32_t smb = s2u(sm);
    const int tid = threadIdx.x, lane = tid & 31, warp = tid >> 5;
    const int wm = warp >> 1, wn = warp & 1;      // 2x2 warp grid, 64x64 tiles
    const int n0 = blockIdx.x * 128;
    const int kb0 = blockIdx.y * NKB;

    const __half* A = (MODE == 0) ? g_zh : g_h;
    const __half* B = (MODE == 0) ? g_W1h : g_W2h;
    float* part = ((MODE == 0) ? g_hpart : g_h2part)
                + (size_t)blockIdx.y * NBATCH * LDO;

    const int am = tid >> 3, ac = tid & 7;
    const int bk = tid >> 4, bc = tid & 15;
    const __half* aptr = A + (size_t)am * LDA + kb0 * 64 + ac * 8;
    const __half* bptr = B + (size_t)(kb0 * 64 + bk) * LDB + n0 + bc * 8;
    const uint32_t aoff = (uint32_t)(am * 128 + ((ac ^ (am & 7)) << 4));
    const uint32_t boff = 16384u + (uint32_t)(bk * 256 + ((bc ^ (bk & 7)) << 4));

    const int hi = lane >> 4, lo7 = lane & 7, lo15 = lane & 15;
    uint32_t baseA[4], swA[4], preB[4];
#pragma unroll
    for (int f = 0; f < 4; f++) baseA[f] = (uint32_t)((wm * 64 + f * 16 + lo15) * 128);
#pragma unroll
    for (int ks = 0; ks < 4; ks++) swA[ks] = (uint32_t)(((ks * 2 + hi) ^ lo7) << 4);
#pragma unroll
    for (int h = 0; h < 4; h++)
        preB[h] = 16384u + (uint32_t)((((wn * 8 + h * 2 + hi) ^ lo7) << 4) + lo15 * 256);

    float acc[4][8][4];
#pragma unroll
    for (int f = 0; f < 4; f++)
#pragma unroll
        for (int t = 0; t < 8; t++)
#pragma unroll
            for (int i = 0; i < 4; i++) acc[f][t][i] = 0.0f;

    auto load_stage = [&](uint32_t stage) {
#pragma unroll
        for (int i = 0; i < 8; i++) {
            cp16(stage + aoff + i * 2048, aptr + (size_t)i * 16 * LDA);
            cp16(stage + boff + i * 2048, bptr + (size_t)i * 8 * LDB);
        }
        aptr += 64;
        bptr += (size_t)64 * LDB;
    };

    uint32_t s0 = smb, s1 = smb + STAGEB, s2 = smb + 2 * STAGEB;

    load_stage(s0);
    asm volatile("cp.async.commit_group;\n");
    load_stage(s1);
    asm volatile("cp.async.commit_group;\n");

#pragma unroll 1
    for (int kb = 0; kb < NKB; kb++) {
        asm volatile("cp.async.wait_group %0;\n" :: "n"(1));
        __syncthreads();
        if (kb + 2 < NKB) load_stage(s2);
        asm volatile("cp.async.commit_group;\n");

#pragma unroll
        for (int ks = 0; ks < 4; ks++) {
            uint32_t a[4][4], bf[8][2];
#pragma unroll
            for (int f = 0; f < 4; f++) {
                asm volatile("ldmatrix.sync.aligned.m8n8.x4.shared.b16 {%0,%1,%2,%3},[%4];\n"
                             : "=r"(a[f][0]), "=r"(a[f][1]), "=r"(a[f][2]), "=r"(a[f][3])
                             : "r"(s0 + baseA[f] + swA[ks]));
            }
#pragma unroll
            for (int h = 0; h < 4; h++) {
                uint32_t r0, r1, r2, r3;
                asm volatile("ldmatrix.sync.aligned.m8n8.x4.trans.shared.b16 {%0,%1,%2,%3},[%4];\n"
                             : "=r"(r0), "=r"(r1), "=r"(r2), "=r"(r3)
                             : "r"(s0 + preB[h] + ks * 4096));
                bf[h * 2][0] = r0; bf[h * 2][1] = r1;
                bf[h * 2 + 1][0] = r2; bf[h * 2 + 1][1] = r3;
            }
#pragma unroll
            for (int f = 0; f < 4; f++)
#pragma unroll
                for (int t = 0; t < 8; t++) {
                    asm volatile(
                        "mma.sync.aligned.m16n8k16.row.col.f32.f16.f16.f32 "
                        "{%0,%1,%2,%3},{%4,%5,%6,%7},{%8,%9},{%0,%1,%2,%3};\n"
                        : "+f"(acc[f][t][0]), "+f"(acc[f][t][1]),
                          "+f"(acc[f][t][2]), "+f"(acc[f][t][3])
                        : "r"(a[f][0]), "r"(a[f][1]), "r"(a[f][2]), "r"(a[f][3]),
                          "r"(bf[t][0]), "r"(bf[t][1]));
                }
        }
        uint32_t tmp = s0; s0 = s1; s1 = s2; s2 = tmp;
    }

#pragma unroll
    for (int f = 0; f < 4; f++) {
        int row = wm * 64 + f * 16 + (lane >> 2);
#pragma unroll
        for (int t = 0; t < 8; t++) {
            int col = n0 + wn * 64 + t * 8 + ((lane & 3) << 1);
            *(float2*)(part + (size_t)row * LDO + col)       = make_float2(acc[f][t][0], acc[f][t][1]);
            *(float2*)(part + (size_t)(row + 8) * LDO + col) = make_float2(acc[f][t][2], acc[f][t][3]);
        }
    }
}

// ---------------- GEMM1 reduce + bias + time-embedding tail + tanh ----------------
__global__ void reduce_tanh_kernel(const float* __restrict__ W1, const float* __restrict__ b1, int t) {
    int idx = blockIdx.x * 256 + threadIdx.x;      // < 128*4096
    int b = idx >> 12, n = idx & 4095;
    float s = b1[n];
#pragma unroll
    for (int p = 0; p < SPLITK1; p++)
        s += g_hpart[(size_t)p * NBATCH * HID + idx];
    const float* e0 = g_emb + (t * NBATCH + b) * 6;
    const float* e1 = e0 + NBATCH * 6;
#pragma unroll
    for (int j = 0; j < 6; j++) s += e0[j] * W1[(size_t)(ZDIM + j) * HID + n];
#pragma unroll
    for (int j = 0; j < 6; j++) s += e1[j] * W1[(size_t)(ZDIM + 6 + j) * HID + n];
    g_h[idx] = __float2half(tanhf(s));
}

// ---------------- GEMM2 reduce: z += p0 + p1 + b2, optionally refresh fp16 z ----------------
__global__ void zupdate_kernel(const float* __restrict__ b2, float* __restrict__ z, int write_zh) {
    int idx = blockIdx.x * 256 + threadIdx.x;
    if (idx >= NBATCH * ZDIM) return;
    int row = idx / ZDIM;
    int col = idx - row * ZDIM;
    size_t po = (size_t)row * N2PAD + col;
    float v = z[idx] + b2[col]
            + g_h2part[po]
            + g_h2part[(size_t)NBATCH * N2PAD + po];
    z[idx] = v;
    if (write_zh) g_zh[(size_t)row * ZPAD + col] = __float2half(v);
}

// ---------------- launcher (capture fork-join: hide convW2 behind step-0 GEMM1) ----------------
extern "C" void kernel_launch(void* const* d_in, const int* in_sizes, int n_in,
                              void* d_out, int out_size) {
    const float* input_freq = (const float*)d_in[0];
    const int*   input_seq  = (const int*)  d_in[1];
    const int*   uid        = (const int*)  d_in[2];
    const float* cur_time   = (const float*)d_in[3];
    const float* tar_time   = (const float*)d_in[4];
    const float* fuse       = (const float*)d_in[5];
    const float* W1         = (const float*)d_in[6];
    const float* b1         = (const float*)d_in[7];
    const float* W2         = (const float*)d_in[8];
    const float* b2         = (const float*)d_in[9];
    const int*   n_poi      = (const int*)  d_in[10];
    float* z = (float*)d_out;

    // One-time host objects (created on the first, uncaptured, correctness call;
    // reused on every call -> identical captured work each time).
    static cudaStream_t s2 = nullptr;
    static cudaEvent_t evZ = nullptr, evW1 = nullptr, evW2 = nullptr;
    if (s2 == nullptr) {
        cudaStreamCreateWithFlags(&s2, cudaStreamNonBlocking);
        cudaEventCreateWithFlags(&evZ,  cudaEventDisableTiming);
        cudaEventCreateWithFlags(&evW1, cudaEventDisableTiming);
        cudaEventCreateWithFlags(&evW2, cudaEventDisableTiming);
        cudaFuncSetAttribute(gemm_kernel<0>, cudaFuncAttributeMaxDynamicSharedMemorySize, SMEM_BYTES);
        cudaFuncSetAttribute(gemm_kernel<1>, cudaFuncAttributeMaxDynamicSharedMemorySize, SMEM_BYTES);
    }

    // fork: s2 handles z0/emb/zpad, then convW2 (after convW1 to avoid DRAM contention)
    cudaEventRecord(evZ, 0);                   // seed fork point on main stream
    cudaStreamWaitEvent(s2, evZ, 0);

    // main stream: convW1 (critical path for GEMM1)
    {
        size_t n1 = (size_t)ZPAD * HID / 8;
        convW1_kernel<<<(unsigned)((n1 + 255) / 256), 256>>>(W1);
        cudaEventRecord(evW1, 0);
    }
    // s2: inputs -> z0/zh, embeddings
    emb_kernel<<<1, 128, 0, s2>>>(cur_time, tar_time);
    z0_kernel<<<(NBATCH * ZDIM + 511) / 512, 512, 0, s2>>>(input_freq, input_seq, uid, fuse, n_poi, z);
    zpad_kernel<<<(NBATCH * (ZPAD - ZDIM) / 2 + 255) / 256, 256, 0, s2>>>();
    cudaEventRecord(evZ, s2);
    // s2: convW2 after convW1 completes (runs concurrently with step-0 GEMM1 + reduce)
    cudaStreamWaitEvent(s2, evW1, 0);
    {
        size_t n2 = (size_t)HID * N2PAD / 8;
        convW2_kernel<<<(unsigned)((n2 + 255) / 256), 256, 0, s2>>>(W2);
        cudaEventRecord(evW2, s2);
    }

    // main stream: join z0-group, then the step loop
    cudaStreamWaitEvent(0, evZ, 0);
    for (int t = 0; t < NSTEPS; t++) {
        gemm_kernel<0><<<dim3(HID / 128, SPLITK1), 128, SMEM_BYTES>>>();
        reduce_tanh_kernel<<<NBATCH * HID / 256, 256>>>(W1, b1, t);
        if (t == 0) cudaStreamWaitEvent(0, evW2, 0);   // join convW2 before first GEMM2
        gemm_kernel<1><<<dim3(N2PAD / 128, SPLITK2), 128, SMEM_BYTES>>>();
        zupdate_kernel<<<(NBATCH * ZDIM + 255) / 256, 256>>>(b2, z, (t < NSTEPS - 1) ? 1 : 0);
    }
}

// round 16
// speedup vs baseline: 1.2464x; 1.0241x over previous
#include <cuda_runtime.h>
#include <cuda_fp16.h>
#include <math.h>
#include <stdint.h>

// ---------------- problem constants ----------------
#define ZDIM   17728      // 3*56*56 + 64*128 + 128
#define ZPAD   18432      // 288*64 : padded K for GEMM1 (9 uniform split-K chunks)
#define HID    4096
#define NBATCH 128
#define N2PAD  17792      // 139*128, padded N for GEMM2
#define NSTEPS 11
#define SPLITK1 9
#define NKB1   32         // 288/9 K-tiles per split group (compile-time)
#define SPLITK2 2
#define NKB2   32         // 64/2

// ---------------- device scratch (no allocs allowed) ----------------
__device__ __half g_W1h[(size_t)ZPAD * HID];       // W1 fp16 [k][n], k padded w/ zeros
__device__ __half g_W2h[(size_t)HID * N2PAD];      // W2 fp16 [k][n], n padded w/ zeros
__device__ __half g_zh [(size_t)NBATCH * ZPAD];    // fp16 z, k-padded w/ zeros
__device__ __half g_h  [(size_t)NBATCH * HID];     // fp16 hidden h
__device__ float  g_hpart [(size_t)SPLITK1 * NBATCH * HID];
__device__ float  g_h2part[(size_t)SPLITK2 * NBATCH * N2PAD];
__device__ float  g_emb[12 * NBATCH * 6];

// ---------------- time grid + embedding ----------------
__global__ void emb_kernel(const float* __restrict__ cur, const float* __restrict__ tar) {
    int b = threadIdx.x;
    if (b >= NBATCH) return;
    const float P[3] = {24.0f, 7.0f, 365.0f};
    float tc[3];
    for (int j = 0; j < 3; j++) tc[j] = cur[b * 3 + j];
    int r = 0;
    for (int j = 0; j < 3; j++) {
        float s = cur[b * 3 + j], e = tar[b * 3 + j];
        bool wrap = s > e;
        float ea = wrap ? e + P[j] : e;
        for (int k = 0; k < 4; k++) {
            float frac = (float)k / 3.0f;
            float inter = s + (ea - s) * frac;
            if (wrap) inter = fmodf(inter, P[j]);
            tc[j] = inter;
            for (int jj = 0; jj < 3; jj++) {
                float ph = 6.2831853071795864769f * tc[jj] / P[jj];
                g_emb[(r * NBATCH + b) * 6 + jj]     = sinf(ph);
                g_emb[(r * NBATCH + b) * 6 + 3 + jj] = cosf(ph);
            }
            r++;
        }
    }
}

// ---------------- z0 build (stride ZPAD for fp16 copy) ----------------
__global__ void z0_kernel(const float* __restrict__ freq, const int* __restrict__ seq,
                          const int* __restrict__ uid, const float* __restrict__ fuse,
                          const int* __restrict__ n_poi, float* __restrict__ zout) {
    int idx = blockIdx.x * blockDim.x + threadIdx.x;
    if (idx >= NBATCH * ZDIM) return;
    int b = idx / ZDIM;
    int c = idx - b * ZDIM;
    float v;
    if (c < 9408) {
        v = freq[b * 3136 + (c % 3136)];
    } else if (c < 17600) {
        int cc = c - 9408;
        int d = cc >> 6, l = cc & 63;
        v = fuse[(size_t)seq[b * 64 + l] * 128 + d];
    } else {
        int d = c - 17600;
        v = fuse[(size_t)(n_poi[0] + uid[b]) * 128 + d];
    }
    zout[idx] = v;
    g_zh[(size_t)b * ZPAD + c] = __float2half(v);
}

// zero the K-pad region of g_zh (cols [ZDIM, ZPAD)) — idempotent
__global__ void zpad_kernel() {
    int i = blockIdx.x * 256 + threadIdx.x;     // half2 units
    if (i >= NBATCH * (ZPAD - ZDIM) / 2) return;
    int b = i / ((ZPAD - ZDIM) / 2);
    int c = (i % ((ZPAD - ZDIM) / 2)) * 2;
    *(__half2*)(g_zh + (size_t)b * ZPAD + ZDIM + c) = __floats2half2_rn(0.f, 0.f);
}

// ---------------- fp32 -> fp16 weight conversion (8 floats/thread, 16B stores) ----------------
__global__ void convW1_kernel(const float* __restrict__ W1) {
    size_t i = (size_t)blockIdx.x * blockDim.x + threadIdx.x;   // oct over [ZPAD][HID]
    const size_t N = (size_t)ZPAD * HID / 8;
    if (i >= N) return;
    int k = (int)(i >> 9);                   // HID/8 = 512
    int n = (int)(i & 511) * 8;
    float4 v0, v1;
    if (k < ZDIM) {
        const float4* s = (const float4*)(W1 + (size_t)k * HID + n);
        v0 = s[0]; v1 = s[1];
    } else {
        v0 = v1 = make_float4(0.f, 0.f, 0.f, 0.f);
    }
    union { __half2 h[4]; uint4 u; } o;
    o.h[0] = __floats2half2_rn(v0.x, v0.y);
    o.h[1] = __floats2half2_rn(v0.z, v0.w);
    o.h[2] = __floats2half2_rn(v1.x, v1.y);
    o.h[3] = __floats2half2_rn(v1.z, v1.w);
    ((uint4*)g_W1h)[i] = o.u;
}

__global__ void convW2_kernel(const float* __restrict__ W2) {
    size_t i = (size_t)blockIdx.x * blockDim.x + threadIdx.x;   // oct over [HID][N2PAD]
    const size_t N = (size_t)HID * N2PAD / 8;
    if (i >= N) return;
    int k = (int)(i / (N2PAD / 8));
    int n = (int)(i % (N2PAD / 8)) * 8;
    float4 v0, v1;
    if (n < ZDIM) {                          // ZDIM%8==0 -> full oct in range
        const float4* s = (const float4*)(W2 + (size_t)k * ZDIM + n);
        v0 = s[0]; v1 = s[1];
    } else {
        v0 = v1 = make_float4(0.f, 0.f, 0.f, 0.f);
    }
    union { __half2 h[4]; uint4 u; } o;
    o.h[0] = __floats2half2_rn(v0.x, v0.y);
    o.h[1] = __floats2half2_rn(v0.z, v0.w);
    o.h[2] = __floats2half2_rn(v1.x, v1.y);
    o.h[3] = __floats2half2_rn(v1.z, v1.w);
    ((uint4*)g_W2h)[i] = o.u;
}

// ---------------- GEMM: 128x128 CTA tile, 4 warps (64x64 each), BK=64, 3-stage cp.async ----------------
#define STAGEB 32768
#define SMEM_BYTES (3 * STAGEB)    // 98304 -> 2 CTAs/SM

__device__ __forceinline__ uint32_t s2u(const void* p) {
    return (uint32_t)__cvta_generic_to_shared(p);
}
__device__ __forceinline__ void cp16(uint32_t dst, const void* src) {
    asm volatile("cp.async.cg.shared.global [%0],[%1],16;\n" :: "r"(dst), "l"(src));
}

// MODE 0: g_hpart [split] = zh @ W1h   (split-K 9, NKB=32)
// MODE 1: g_h2part[split] = h  @ W2h   (split-K 2, NKB=32)
template <int MODE>
__global__ __launch_bounds__(128, 2) void gemm_kernel() {
    constexpr int LDA = (MODE == 0) ? ZPAD : HID;
    constexpr int LDB = (MODE == 0) ? HID  : N2PAD;
    constexpr int LDO = (MODE == 0) ? HID  : N2PAD;
    constexpr int NKB = (MODE == 0) ? NKB1 : NKB2;

    extern __shared__ char sm[];
    const uint32_t smb = s2u(sm);
    const int tid = threadIdx.x, lane = tid & 31, warp = tid >> 5;
    const int wm = warp >> 1, wn = warp & 1;      // 2x2 warp grid, 64x64 tiles
    const int n0 = blockIdx.x * 128;
    const int kb0 = blockIdx.y * NKB;

    const __half* A = (MODE == 0) ? g_zh : g_h;
    const __half* B = (MODE == 0) ? g_W1h : g_W2h;
    float* part = ((MODE == 0) ? g_hpart : g_h2part)
                + (size_t)blockIdx.y * NBATCH * LDO;

    const int am = tid >> 3, ac = tid & 7;
    const int bk = tid >> 4, bc = tid & 15;
    const __half* aptr = A + (size_t)am * LDA + kb0 * 64 + ac * 8;
    const __half* bptr = B + (size_t)(kb0 * 64 + bk) * LDB + n0 + bc * 8;
    const uint32_t aoff = (uint32_t)(am * 128 + ((ac ^ (am & 7)) << 4));
    const uint32_t boff = 16384u + (uint32_t)(bk * 256 + ((bc ^ (bk & 7)) << 4));

    const int hi = lane >> 4, lo7 = lane & 7, lo15 = lane & 15;
    uint32_t baseA[4], swA[4], preB[4];
#pragma unroll
    for (int f = 0; f < 4; f++) baseA[f] = (uint32_t)((wm * 64 + f * 16 + lo15) * 128);
#pragma unroll
    for (int ks = 0; ks < 4; ks++) swA[ks] = (uint32_t)(((ks * 2 + hi) ^ lo7) << 4);
#pragma unroll
    for (int h = 0; h < 4; h++)
        preB[h] = 16384u + (uint32_t)((((wn * 8 + h * 2 + hi) ^ lo7) << 4) + lo15 * 256);

    float acc[4][8][4];
#pragma unroll
    for (int f = 0; f < 4; f++)
#pragma unroll
        for (int t = 0; t < 8; t++)
#pragma unroll
            for (int i = 0; i < 4; i++) acc[f][t][i] = 0.0f;

    auto load_stage = [&](uint32_t stage) {
#pragma unroll
        for (int i = 0; i < 8; i++) {
            cp16(stage + aoff + i * 2048, aptr + (size_t)i * 16 * LDA);
            cp16(stage + boff + i * 2048, bptr + (size_t)i * 8 * LDB);
        }
        aptr += 64;
        bptr += (size_t)64 * LDB;
    };

    uint32_t s0 = smb, s1 = smb + STAGEB, s2 = smb + 2 * STAGEB;

    load_stage(s0);
    asm volatile("cp.async.commit_group;\n");
    load_stage(s1);
    asm volatile("cp.async.commit_group;\n");

#pragma unroll 1
    for (int kb = 0; kb < NKB; kb++) {
        asm volatile("cp.async.wait_group %0;\n" :: "n"(1));
        __syncthreads();
        if (kb + 2 < NKB) load_stage(s2);
        asm volatile("cp.async.commit_group;\n");

#pragma unroll
        for (int ks = 0; ks < 4; ks++) {
            uint32_t a[4][4], bf[8][2];
#pragma unroll
            for (int f = 0; f < 4; f++) {
                asm volatile("ldmatrix.sync.aligned.m8n8.x4.shared.b16 {%0,%1,%2,%3},[%4];\n"
                             : "=r"(a[f][0]), "=r"(a[f][1]), "=r"(a[f][2]), "=r"(a[f][3])
                             : "r"(s0 + baseA[f] + swA[ks]));
            }
#pragma unroll
            for (int h = 0; h < 4; h++) {
                uint32_t r0, r1, r2, r3;
                asm volatile("ldmatrix.sync.aligned.m8n8.x4.trans.shared.b16 {%0,%1,%2,%3},[%4];\n"
                             : "=r"(r0), "=r"(r1), "=r"(r2), "=r"(r3)
                             : "r"(s0 + preB[h] + ks * 4096));
                bf[h * 2][0] = r0; bf[h * 2][1] = r1;
                bf[h * 2 + 1][0] = r2; bf[h * 2 + 1][1] = r3;
            }
#pragma unroll
            for (int f = 0; f < 4; f++)
#pragma unroll
                for (int t = 0; t < 8; t++) {
                    asm volatile(
                        "mma.sync.aligned.m16n8k16.row.col.f32.f16.f16.f32 "
                        "{%0,%1,%2,%3},{%4,%5,%6,%7},{%8,%9},{%0,%1,%2,%3};\n"
                        : "+f"(acc[f][t][0]), "+f"(acc[f][t][1]),
                          "+f"(acc[f][t][2]), "+f"(acc[f][t][3])
                        : "r"(a[f][0]), "r"(a[f][1]), "r"(a[f][2]), "r"(a[f][3]),
                          "r"(bf[t][0]), "r"(bf[t][1]));
                }
        }
        uint32_t tmp = s0; s0 = s1; s1 = s2; s2 = tmp;
    }

#pragma unroll
    for (int f = 0; f < 4; f++) {
        int row = wm * 64 + f * 16 + (lane >> 2);
#pragma unroll
        for (int t = 0; t < 8; t++) {
            int col = n0 + wn * 64 + t * 8 + ((lane & 3) << 1);
            *(float2*)(part + (size_t)row * LDO + col)       = make_float2(acc[f][t][0], acc[f][t][1]);
            *(float2*)(part + (size_t)(row + 8) * LDO + col) = make_float2(acc[f][t][2], acc[f][t][3]);
        }
    }
}

// ---------------- GEMM1 reduce + bias + time-embedding tail + tanh (scalar, R13-proven) ----------------
__global__ void reduce_tanh_kernel(const float* __restrict__ W1, const float* __restrict__ b1, int t) {
    int idx = blockIdx.x * 256 + threadIdx.x;      // < 128*4096
    int b = idx >> 12, n = idx & 4095;
    float s = b1[n];
#pragma unroll
    for (int p = 0; p < SPLITK1; p++)
        s += g_hpart[(size_t)p * NBATCH * HID + idx];
    const float* e0 = g_emb + (t * NBATCH + b) * 6;
    const float* e1 = e0 + NBATCH * 6;
#pragma unroll
    for (int j = 0; j < 6; j++) s += e0[j] * W1[(size_t)(ZDIM + j) * HID + n];
#pragma unroll
    for (int j = 0; j < 6; j++) s += e1[j] * W1[(size_t)(ZDIM + 6 + j) * HID + n];
    g_h[idx] = __float2half(tanhf(s));
}

// ---------------- GEMM2 reduce (float4): z += p0 + p1 + b2, optionally refresh fp16 z ----------------
__global__ void zupdate_kernel(const float* __restrict__ b2, float* __restrict__ z, int write_zh) {
    int i4 = blockIdx.x * 256 + threadIdx.x;       // float4 units
    if (i4 >= NBATCH * ZDIM / 4) return;
    int row = i4 / (ZDIM / 4);
    int col = (i4 - row * (ZDIM / 4)) * 4;
    size_t zo = (size_t)row * ZDIM + col;
    size_t po = (size_t)row * N2PAD + col;
    float4 zv = *(float4*)(z + zo);
    float4 bv = *(const float4*)(b2 + col);
    float4 a0 = *(const float4*)(g_h2part + po);
    float4 a1 = *(const float4*)(g_h2part + (size_t)NBATCH * N2PAD + po);
    float4 v;
    v.x = zv.x + bv.x + a0.x + a1.x;
    v.y = zv.y + bv.y + a0.y + a1.y;
    v.z = zv.z + bv.z + a0.z + a1.z;
    v.w = zv.w + bv.w + a0.w + a1.w;
    *(float4*)(z + zo) = v;
    if (write_zh) {
        union { __half2 h[2]; uint2 u; } o;
        o.h[0] = __floats2half2_rn(v.x, v.y);
        o.h[1] = __floats2half2_rn(v.z, v.w);
        *(uint2*)(g_zh + (size_t)row * ZPAD + col) = o.u;
    }
}

// ---------------- launcher (capture fork-join: hide convW2 behind step-0 GEMM1) ----------------
extern "C" void kernel_launch(void* const* d_in, const int* in_sizes, int n_in,
                              void* d_out, int out_size) {
    const float* input_freq = (const float*)d_in[0];
    const int*   input_seq  = (const int*)  d_in[1];
    const int*   uid        = (const int*)  d_in[2];
    const float* cur_time   = (const float*)d_in[3];
    const float* tar_time   = (const float*)d_in[4];
    const float* fuse       = (const float*)d_in[5];
    const float* W1         = (const float*)d_in[6];
    const float* b1         = (const float*)d_in[7];
    const float* W2         = (const float*)d_in[8];
    const float* b2         = (const float*)d_in[9];
    const int*   n_poi      = (const int*)  d_in[10];
    float* z = (float*)d_out;

    static cudaStream_t s2 = nullptr;
    static cudaEvent_t evZ = nullptr, evW1 = nullptr, evW2 = nullptr;
    if (s2 == nullptr) {
        cudaStreamCreateWithFlags(&s2, cudaStreamNonBlocking);
        cudaEventCreateWithFlags(&evZ,  cudaEventDisableTiming);
        cudaEventCreateWithFlags(&evW1, cudaEventDisableTiming);
        cudaEventCreateWithFlags(&evW2, cudaEventDisableTiming);
        cudaFuncSetAttribute(gemm_kernel<0>, cudaFuncAttributeMaxDynamicSharedMemorySize, SMEM_BYTES);
        cudaFuncSetAttribute(gemm_kernel<1>, cudaFuncAttributeMaxDynamicSharedMemorySize, SMEM_BYTES);
    }

    // fork: s2 handles z0/emb/zpad, then convW2 (after convW1 to avoid DRAM contention)
    cudaEventRecord(evZ, 0);
    cudaStreamWaitEvent(s2, evZ, 0);

    // main stream: convW1 (critical path for GEMM1)
    {
        size_t n1 = (size_t)ZPAD * HID / 8;
        convW1_kernel<<<(unsigned)((n1 + 255) / 256), 256>>>(W1);
        cudaEventRecord(evW1, 0);
    }
    // s2: inputs -> z0/zh, embeddings
    emb_kernel<<<1, 128, 0, s2>>>(cur_time, tar_time);
    z0_kernel<<<(NBATCH * ZDIM + 511) / 512, 512, 0, s2>>>(input_freq, input_seq, uid, fuse, n_poi, z);
    zpad_kernel<<<(NBATCH * (ZPAD - ZDIM) / 2 + 255) / 256, 256, 0, s2>>>();
    cudaEventRecord(evZ, s2);
    cudaStreamWaitEvent(s2, evW1, 0);
    {
        size_t n2 = (size_t)HID * N2PAD / 8;
        convW2_kernel<<<(unsigned)((n2 + 255) / 256), 256, 0, s2>>>(W2);
        cudaEventRecord(evW2, s2);
    }

    // main stream: join z0-group, then the step loop
    cudaStreamWaitEvent(0, evZ, 0);
    for (int t = 0; t < NSTEPS; t++) {
        gemm_kernel<0><<<dim3(HID / 128, SPLITK1), 128, SMEM_BYTES>>>();
        reduce_tanh_kernel<<<NBATCH * HID / 256, 256>>>(W1, b1, t);
        if (t == 0) cudaStreamWaitEvent(0, evW2, 0);
        gemm_kernel<1><<<dim3(N2PAD / 128, SPLITK2), 128, SMEM_BYTES>>>();
        zupdate_kernel<<<(NBATCH * ZDIM / 4 + 255) / 256, 256>>>(b2, z, (t < NSTEPS - 1) ? 1 : 0);
    }
}